// round 16
// baseline (speedup 1.0000x reference)
#include <cuda_runtime.h>
#include <cuda_fp16.h>
#include <math.h>

#define BATCH   2
#define SEQ     2048
#define DMODEL  1024
#define NHEADS  16
#define DK      64
#define NTOK    (BATCH*SEQ)      /* 4096 */
#define E3      (3*DMODEL)       /* 3072 */
#define NTQ     (SEQ/128)        /* 16 q-tiles */

// Scratch (allocation-free rule: __device__ globals)
__device__ float  g_qf32[(size_t)NTOK * DMODEL];   // roped Q, fp32
__device__ __half g_kh[(size_t)NTOK * DMODEL];     // roped K, fp16
__device__ __half g_vh[(size_t)NTOK * DMODEL];     // V, fp16
__device__ __half g_ah[(size_t)NTOK * DMODEL];     // attn out, fp16

// ---------------------------------------------------------------------------
__device__ __forceinline__ unsigned pack_h(float a, float b)
{
    __half2 h = __floats2half2_rn(a, b);
    return *reinterpret_cast<unsigned*>(&h);
}

// ---------------------------------------------------------------------------
#define MMA16816(d, a, b0, b1)                                                 \
    asm volatile("mma.sync.aligned.m16n8k16.row.col.f32.f16.f16.f32 "          \
                 "{%0,%1,%2,%3}, {%4,%5,%6,%7}, {%8,%9}, {%0,%1,%2,%3};"       \
                 : "+f"(d[0]), "+f"(d[1]), "+f"(d[2]), "+f"(d[3])              \
                 : "r"(a[0]), "r"(a[1]), "r"(a[2]), "r"(a[3]), "r"(b0), "r"(b1))

#define LDSM4(r0, r1, r2, r3, addr)                                            \
    asm volatile("ldmatrix.sync.aligned.m8n8.x4.shared.b16 {%0,%1,%2,%3}, [%4];" \
                 : "=r"(r0), "=r"(r1), "=r"(r2), "=r"(r3) : "r"(addr))

#define LDSM4T(r0, r1, r2, r3, addr)                                           \
    asm volatile("ldmatrix.sync.aligned.m8n8.x4.trans.shared.b16 {%0,%1,%2,%3}, [%4];" \
                 : "=r"(r0), "=r"(r1), "=r"(r2), "=r"(r3) : "r"(addr))

// ---------------------------------------------------------------------------
// Register-staged fp16 GEMM mainloop (128x128x32 tiles, double-buffered smem).
// fp32 operands are converted to fp16 in registers during staging (fuses the
// old cvt_all pass into the GEMMs). ldmatrix + mma section unchanged.
// ---------------------------------------------------------------------------
#define ARR_HALVES (128*40)
#define RS_STG     (2*ARR_HALVES)
#define GEMM_SMEM  (2*RS_STG*2)   /* 40960 bytes */

// common prologue: indices, accumulators, smem bases
#define GEMM_COMMON(Kdim)                                                      \
    extern __shared__ __half dynsmem[];                                        \
    const unsigned sbase = (unsigned)__cvta_generic_to_shared(dynsmem);        \
    const int tid  = threadIdx.x;                                              \
    const int lane = tid & 31;                                                 \
    const int wid  = tid >> 5;                                                 \
    const int warpM = wid & 3;                                                 \
    const int warpN = wid >> 2;                                                \
    const int m0 = blockIdx.y * 128;                                           \
    const int n0 = blockIdx.x * 128;                                           \
    const int g  = lane >> 2;                                                  \
    const int tg = lane & 3;                                                   \
    float acc[2][8][4] = {};                                                   \
    const int rr  = tid >> 2;                                                  \
    const int ccf = (tid & 3) << 3;                                            \
    const unsigned so0 = (unsigned)(rr*40 + ccf) * 2;                          \
    const unsigned so1 = so0 + 64*40*2;                                        \
    const unsigned lm_off =                                                    \
        ((unsigned)((lane & 15) * 40 + ((lane >> 4) << 3))) * 2;               \
    const unsigned a_base = sbase + (unsigned)(warpM * 32) * 80 + lm_off;      \
    const unsigned b_base = sbase + (unsigned)(warpN * 64) * 80 + lm_off;      \
    const int nch = Kdim / 32;

// compute section on stage buf (identical mma order to R13/R14)
#define GEMM_COMPUTE(buf)                                                      \
    do {                                                                       \
        const unsigned st = (unsigned)(buf) * (RS_STG * 2);                    \
        _Pragma("unroll")                                                      \
        for (int ks = 0; ks < 2; ks++) {                                       \
            const unsigned kb2 = (unsigned)(ks * 16) * 2;                      \
            unsigned ah[2][4];                                                 \
            _Pragma("unroll")                                                  \
            for (int mi = 0; mi < 2; mi++) {                                   \
                unsigned aa = a_base + st + (unsigned)(mi * 16) * 80 + kb2;    \
                LDSM4(ah[mi][0], ah[mi][1], ah[mi][2], ah[mi][3], aa);         \
            }                                                                  \
            _Pragma("unroll")                                                  \
            for (int nip = 0; nip < 4; nip++) {                                \
                unsigned ba = b_base + st + ARR_HALVES*2                       \
                            + (unsigned)(nip * 16) * 80 + kb2;                 \
                unsigned b0e, b0o_, b1e, b1o_;                                 \
                LDSM4(b0e, b0o_, b1e, b1o_, ba);                               \
                _Pragma("unroll")                                              \
                for (int mi = 0; mi < 2; mi++) {                               \
                    MMA16816(acc[mi][2*nip],   ah[mi], b0e, b1e);              \
                    MMA16816(acc[mi][2*nip+1], ah[mi], b0o_, b1o_);            \
                }                                                              \
            }                                                                  \
        }                                                                      \
    } while (0)

// pack 8 fp32 (two float4) into one uint4 of 8 fp16
#define PACK8(v0, v1)                                                          \
    make_uint4(pack_h((v0).x,(v0).y), pack_h((v0).z,(v0).w),                   \
               pack_h((v1).x,(v1).y), pack_h((v1).z,(v1).w))

// ---------------------------------------------------------------------------
// QKV GEMM: A = x (fp32), B = w_qkv (fp32); conversion fused into staging.
// Fused RoPE + dtype-split epilogue (unchanged from R12-R14).
// ---------------------------------------------------------------------------
__global__ __launch_bounds__(256, 2)
void qkv_gemm_kernel(const float* __restrict__ x,
                     const float* __restrict__ wq,
                     const int* __restrict__ pos)
{
    GEMM_COMMON(DMODEL)

    const float* pA0 = &x [(size_t)(m0 + rr)      * DMODEL + ccf];
    const float* pA1 = &x [(size_t)(m0 + rr + 64) * DMODEL + ccf];
    const float* pB0 = &wq[(size_t)(n0 + rr)      * DMODEL + ccf];
    const float* pB1 = &wq[(size_t)(n0 + rr + 64) * DMODEL + ccf];

    float4 a00, a01, a10, a11, b00, b01, b10, b11;

    #define GLF()                                                              \
        do {                                                                   \
            a00 = *(const float4*)pA0;  a01 = *(const float4*)(pA0 + 4);       \
            a10 = *(const float4*)pA1;  a11 = *(const float4*)(pA1 + 4);       \
            b00 = *(const float4*)pB0;  b01 = *(const float4*)(pB0 + 4);       \
            b10 = *(const float4*)pB1;  b11 = *(const float4*)(pB1 + 4);       \
            pA0 += 32; pA1 += 32; pB0 += 32; pB1 += 32;                        \
        } while (0)

    #define STSF(s)                                                            \
        do {                                                                   \
            char* bp = (char*)dynsmem + (size_t)(s) * (RS_STG * 2);            \
            *(uint4*)(bp + so0)                  = PACK8(a00, a01);            \
            *(uint4*)(bp + so1)                  = PACK8(a10, a11);            \
            *(uint4*)(bp + ARR_HALVES*2 + so0)   = PACK8(b00, b01);            \
            *(uint4*)(bp + ARR_HALVES*2 + so1)   = PACK8(b10, b11);            \
        } while (0)

    GLF();
    STSF(0);
    __syncthreads();

    for (int ch = 0; ch < nch; ch++) {
        const int buf = ch & 1;
        if (ch + 1 < nch) { GLF(); }
        GEMM_COMPUTE(buf);
        if (ch + 1 < nch) { STSF(buf ^ 1); }
        __syncthreads();
    }
    #undef GLF
    #undef STSF

    const int region = (blockIdx.x * 128) >> 10;   // 0=Q, 1=K, 2=V

    #pragma unroll
    for (int mi = 0; mi < 2; mi++) {
        int r0 = m0 + warpM*32 + mi*16 + g;
        float p0 = (float)pos[r0 & (SEQ-1)];
        float p1 = (float)pos[(r0+8) & (SEQ-1)];
        #pragma unroll
        for (int ni = 0; ni < 8; ni++) {
            int cg  = n0 + warpN*64 + ni*8 + tg*2;
            int col = cg & (DMODEL-1);
            float x0 = acc[mi][ni][0], y0 = acc[mi][ni][1];
            float x1 = acc[mi][ni][2], y1 = acc[mi][ni][3];
            if (region < 2) {   // rope for Q and K
                int i = (col & 63) >> 1;
                float inv = expf(-((float)i * (1.0f/32.0f)) * 9.2103403719761836f);
                float sn0, cs0, sn1, cs1;
                sincosf(p0 * inv, &sn0, &cs0);
                sincosf(p1 * inv, &sn1, &cs1);
                float t;
                t = x0*cs0 - y0*sn0; y0 = x0*sn0 + y0*cs0; x0 = t;
                t = x1*cs1 - y1*sn1; y1 = x1*sn1 + y1*cs1; x1 = t;
            }
            size_t o0 = (size_t)r0 * DMODEL + col;
            size_t o1 = (size_t)(r0+8) * DMODEL + col;
            if (region == 0) {
                *(float2*)&g_qf32[o0] = make_float2(x0, y0);
                *(float2*)&g_qf32[o1] = make_float2(x1, y1);
            } else if (region == 1) {
                *(unsigned*)&g_kh[o0] = pack_h(x0, y0);
                *(unsigned*)&g_kh[o1] = pack_h(x1, y1);
            } else {
                *(unsigned*)&g_vh[o0] = pack_h(x0, y0);
                *(unsigned*)&g_vh[o1] = pack_h(x1, y1);
            }
        }
    }
}

// ---------------------------------------------------------------------------
// Output GEMM: A = g_ah (fp16, direct copy), B = w_o (fp32, fused convert).
// ---------------------------------------------------------------------------
__global__ __launch_bounds__(256, 2)
void out_gemm_kernel(const float* __restrict__ wo, float* __restrict__ out)
{
    GEMM_COMMON(DMODEL)

    const __half* pA0 = &g_ah[(size_t)(m0 + rr)      * DMODEL + ccf];
    const __half* pA1 = &g_ah[(size_t)(m0 + rr + 64) * DMODEL + ccf];
    const float*  pB0 = &wo  [(size_t)(n0 + rr)      * DMODEL + ccf];
    const float*  pB1 = &wo  [(size_t)(n0 + rr + 64) * DMODEL + ccf];

    uint4 qa0, qa1;
    float4 b00, b01, b10, b11;

    #define GLO()                                                              \
        do {                                                                   \
            qa0 = *(const uint4*)pA0;                                          \
            qa1 = *(const uint4*)pA1;                                          \
            b00 = *(const float4*)pB0;  b01 = *(const float4*)(pB0 + 4);       \
            b10 = *(const float4*)pB1;  b11 = *(const float4*)(pB1 + 4);       \
            pA0 += 32; pA1 += 32; pB0 += 32; pB1 += 32;                        \
        } while (0)

    #define STSO(s)                                                            \
        do {                                                                   \
            char* bp = (char*)dynsmem + (size_t)(s) * (RS_STG * 2);            \
            *(uint4*)(bp + so0)                  = qa0;                        \
            *(uint4*)(bp + so1)                  = qa1;                        \
            *(uint4*)(bp + ARR_HALVES*2 + so0)   = PACK8(b00, b01);            \
            *(uint4*)(bp + ARR_HALVES*2 + so1)   = PACK8(b10, b11);            \
        } while (0)

    GLO();
    STSO(0);
    __syncthreads();

    for (int ch = 0; ch < nch; ch++) {
        const int buf = ch & 1;
        if (ch + 1 < nch) { GLO(); }
        GEMM_COMPUTE(buf);
        if (ch + 1 < nch) { STSO(buf ^ 1); }
        __syncthreads();
    }
    #undef GLO
    #undef STSO

    #pragma unroll
    for (int mi = 0; mi < 2; mi++) {
        int r0 = m0 + warpM*32 + mi*16 + g;
        #pragma unroll
        for (int ni = 0; ni < 8; ni++) {
            int c = n0 + warpN*64 + ni*8 + tg*2;
            *(float2*)&out[(size_t)r0 * DMODEL + c] =
                make_float2(acc[mi][ni][0], acc[mi][ni][1]);
            *(float2*)&out[(size_t)(r0+8) * DMODEL + c] =
                make_float2(acc[mi][ni][2], acc[mi][ni][3]);
        }
    }
}

// ---------------------------------------------------------------------------
// Causal flash attention, fp16 tensor cores (unchanged from R14).
// ---------------------------------------------------------------------------
__global__ __launch_bounds__(256)
void attn_mma_kernel()
{
    const int h   = blockIdx.y;
    const int b   = blockIdx.z;
    const int tid = threadIdx.x;
    const int lane = tid & 31;
    const int w   = tid >> 5;
    const int g   = lane >> 2;
    const int tg  = lane & 3;

    __shared__ __half sKh[2][64*72], sVh[2][64*72];

    const unsigned skh0 = (unsigned)__cvta_generic_to_shared(&sKh[0][0]);
    const unsigned skh1 = (unsigned)__cvta_generic_to_shared(&sKh[1][0]);
    const unsigned svh0 = (unsigned)__cvta_generic_to_shared(&sVh[0][0]);
    const unsigned svh1 = (unsigned)__cvta_generic_to_shared(&sVh[1][0]);

    const unsigned koff = ((((lane >> 4) & 1) * 8 + (lane & 7)) * 72
                          + ((lane >> 3) & 1) * 8) * 2;
    const unsigned voff = ((((lane >> 3) & 1) * 8 + (lane & 7)) * 72
                          + ((lane >> 4) & 1) * 8) * 2;

    const float scale = 0.125f * 1.44269504088896f;   // 1/sqrt(64) * log2(e)

    uint4 pk2[2], pv2[2];

    #define GLT(kt_)                                                           \
        _Pragma("unroll")                                                      \
        for (int i = 0; i < 2; i++) {                                          \
            int idx = tid + i*256;                                             \
            int r = idx >> 3, c8 = (idx & 7) << 3;                             \
            size_t base = ((size_t)(b*SEQ) + (kt_)*64 + r)*DMODEL + h*DK + c8; \
            pk2[i] = *(const uint4*)&g_kh[base];                               \
            pv2[i] = *(const uint4*)&g_vh[base];                               \
        }

    #define STS_T(buf_)                                                        \
        _Pragma("unroll")                                                      \
        for (int i = 0; i < 2; i++) {                                          \
            int idx = tid + i*256;                                             \
            int r = idx >> 3, c8 = (idx & 7) << 3;                             \
            *(uint4*)&sKh[buf_][r*72 + c8] = pk2[i];                           \
            *(uint4*)&sVh[buf_][r*72 + c8] = pv2[i];                           \
        }

    #pragma unroll 1
    for (int half = 0; half < 2; half++) {
        const int qt = half ? (NTQ - 1 - blockIdx.x) : blockIdx.x;
        const int qbase = qt * 128;
        const int row0 = qbase + w*16 + g;
        const int row1 = row0 + 8;
        const int wrowmax = qbase + w*16 + 15;

        unsigned qh[4][4];
        {
            const float* q0 = &g_qf32[((size_t)(b*SEQ) + row0)*DMODEL + h*DK];
            const float* q1 = &g_qf32[((size_t)(b*SEQ) + row1)*DMODEL + h*DK];
            #pragma unroll
            for (int kk = 0; kk < 4; kk++) {
                int d0 = kk*16 + 2*tg;
                float2 a0 = *(const float2*)&q0[d0];
                float2 a1 = *(const float2*)&q1[d0];
                float2 a2 = *(const float2*)&q0[d0+8];
                float2 a3 = *(const float2*)&q1[d0+8];
                qh[kk][0] = pack_h(a0.x*scale, a0.y*scale);
                qh[kk][1] = pack_h(a1.x*scale, a1.y*scale);
                qh[kk][2] = pack_h(a2.x*scale, a2.y*scale);
                qh[kk][3] = pack_h(a3.x*scale, a3.y*scale);
            }
        }

        float o[8][4] = {};
        float m0 = -1e30f, m1 = -1e30f, l0 = 0.f, l1 = 0.f;

        const int ntiles = 2*qt + 2;

        GLT(0);
        STS_T(0);
        __syncthreads();

        for (int kt = 0; kt < ntiles; kt++) {
            const int kvbase = kt * 64;
            const int buf = kt & 1;
            const unsigned kb = (buf ? skh1 : skh0) + koff;
            const unsigned vb = (buf ? svh1 : svh0) + voff;

            if (kt + 1 < ntiles) { GLT(kt + 1); }

            if (kvbase <= wrowmax) {
                float sc[8][4] = {};

                #pragma unroll
                for (int kk = 0; kk < 4; kk++) {
                    #pragma unroll
                    for (int ni = 0; ni < 8; ni += 2) {
                        unsigned bb0, bb1, bb2, bb3;
                        unsigned addr = kb + (unsigned)(ni*576 + kk*16) * 2;
                        LDSM4(bb0, bb1, bb2, bb3, addr);
                        MMA16816(sc[ni],   qh[kk], bb0, bb1);
                        MMA16816(sc[ni+1], qh[kk], bb2, bb3);
                    }
                }

                if (kvbase + 63 > row0) {
                    #pragma unroll
                    for (int ni = 0; ni < 8; ni++) {
                        int c = kvbase + ni*8 + 2*tg;
                        if (c     > row0) sc[ni][0] = -1e30f;
                        if (c + 1 > row0) sc[ni][1] = -1e30f;
                        if (c     > row1) sc[ni][2] = -1e30f;
                        if (c + 1 > row1) sc[ni][3] = -1e30f;
                    }
                }

                float t0 = -1e30f, t1 = -1e30f;
                #pragma unroll
                for (int ni = 0; ni < 8; ni++) {
                    t0 = fmaxf(t0, fmaxf(sc[ni][0], sc[ni][1]));
                    t1 = fmaxf(t1, fmaxf(sc[ni][2], sc[ni][3]));
                }
                t0 = fmaxf(t0, __shfl_xor_sync(0xffffffffu, t0, 1));
                t0 = fmaxf(t0, __shfl_xor_sync(0xffffffffu, t0, 2));
                t1 = fmaxf(t1, __shfl_xor_sync(0xffffffffu, t1, 1));
                t1 = fmaxf(t1, __shfl_xor_sync(0xffffffffu, t1, 2));

                float m0n = fmaxf(m0, t0), m1n = fmaxf(m1, t1);
                float c0 = exp2f(m0 - m0n), c1 = exp2f(m1 - m1n);
                m0 = m0n; m1 = m1n;
                l0 *= c0;  l1 *= c1;
                #pragma unroll
                for (int ni = 0; ni < 8; ni++) {
                    o[ni][0] *= c0; o[ni][1] *= c0;
                    o[ni][2] *= c1; o[ni][3] *= c1;
                }

                #pragma unroll
                for (int ni = 0; ni < 8; ni++) {
                    sc[ni][0] = exp2f(sc[ni][0] - m0);
                    sc[ni][1] = exp2f(sc[ni][1] - m0);
                    sc[ni][2] = exp2f(sc[ni][2] - m1);
                    sc[ni][3] = exp2f(sc[ni][3] - m1);
                    l0 += sc[ni][0] + sc[ni][1];
                    l1 += sc[ni][2] + sc[ni][3];
                }

                #pragma unroll
                for (int kk = 0; kk < 4; kk++) {
                    unsigned ph[4];
                    ph[0] = pack_h(sc[2*kk][0],   sc[2*kk][1]);
                    ph[1] = pack_h(sc[2*kk][2],   sc[2*kk][3]);
                    ph[2] = pack_h(sc[2*kk+1][0], sc[2*kk+1][1]);
                    ph[3] = pack_h(sc[2*kk+1][2], sc[2*kk+1][3]);
                    #pragma unroll
                    for (int nd = 0; nd < 8; nd += 2) {
                        unsigned bb0, bb1, bb2, bb3;
                        unsigned addr = vb + (unsigned)(kk*16*72 + nd*8) * 2;
                        LDSM4T(bb0, bb1, bb2, bb3, addr);
                        MMA16816(o[nd],   ph, bb0, bb1);
                        MMA16816(o[nd+1], ph, bb2, bb3);
                    }
                }
            }

            if (kt + 1 < ntiles) { STS_T(buf ^ 1); }
            __syncthreads();
        }

        l0 += __shfl_xor_sync(0xffffffffu, l0, 1);
        l0 += __shfl_xor_sync(0xffffffffu, l0, 2);
        l1 += __shfl_xor_sync(0xffffffffu, l1, 1);
        l1 += __shfl_xor_sync(0xffffffffu, l1, 2);
        float inv0 = 1.f / l0, inv1 = 1.f / l1;

        size_t base0 = ((size_t)(b*SEQ) + row0)*DMODEL + h*DK;
        size_t base1 = ((size_t)(b*SEQ) + row1)*DMODEL + h*DK;
        #pragma unroll
        for (int nd = 0; nd < 8; nd++) {
            int c = nd*8 + 2*tg;
            *(unsigned*)&g_ah[base0 + c] = pack_h(o[nd][0]*inv0, o[nd][1]*inv0);
            *(unsigned*)&g_ah[base1 + c] = pack_h(o[nd][2]*inv1, o[nd][3]*inv1);
        }
    }
    #undef GLT
    #undef STS_T
}

// ---------------------------------------------------------------------------
extern "C" void kernel_launch(void* const* d_in, const int* in_sizes, int n_in,
                              void* d_out, int out_size)
{
    const float* x      = (const float*)d_in[0];
    const int*   pos    = (const int*)d_in[1];
    const float* w_qkv  = (const float*)d_in[2];
    const float* w_o    = (const float*)d_in[3];
    float*       out    = (float*)d_out;

    // 1) QKV projection (fp32 inputs, fused cvt + RoPE + dtype split)
    {
        dim3 grid(E3 / 128, NTOK / 128);
        qkv_gemm_kernel<<<grid, 256, GEMM_SMEM>>>(x, w_qkv, pos);
    }
    // 2) Causal flash attention
    {
        dim3 grid(NTQ / 2, NHEADS, BATCH);
        attn_mma_kernel<<<grid, 256>>>();
    }
    // 3) Output projection (fused w_o cvt)
    {
        dim3 grid(DMODEL / 128, NTOK / 128);
        out_gemm_kernel<<<grid, 256, GEMM_SMEM>>>(w_o, out);
    }
}

// round 17
// speedup vs baseline: 1.1830x; 1.1830x over previous
#include <cuda_runtime.h>
#include <cuda_fp16.h>
#include <math.h>

#define BATCH   2
#define SEQ     2048
#define DMODEL  1024
#define NHEADS  16
#define DK      64
#define NTOK    (BATCH*SEQ)      /* 4096 */
#define E3      (3*DMODEL)       /* 3072 */
#define NTQ     (SEQ/128)        /* 16 q-tiles */

// Scratch (allocation-free rule: __device__ globals)
__device__ float  g_qf32[(size_t)NTOK * DMODEL];   // roped Q, fp32
__device__ __half g_kh[(size_t)NTOK * DMODEL];     // roped K, fp16
__device__ __half g_vh[(size_t)NTOK * DMODEL];     // V, fp16
__device__ __half g_xh[(size_t)NTOK * DMODEL];
__device__ __half g_wqh[(size_t)E3 * DMODEL];
__device__ __half g_woh[(size_t)DMODEL*DMODEL];
__device__ __half g_ah[(size_t)NTOK * DMODEL];

// ---------------------------------------------------------------------------
__device__ __forceinline__ unsigned pack_h(float a, float b)
{
    __half2 h = __floats2half2_rn(a, b);
    return *reinterpret_cast<unsigned*>(&h);
}

// one launch converts x, w_qkv, w_o to fp16 (segment-dispatched)
#define CVT_NX  (NTOK*DMODEL/4)
#define CVT_NQ  (E3*DMODEL/4)
#define CVT_NO  (DMODEL*DMODEL/4)
#define CVT_TOT (CVT_NX + CVT_NQ + CVT_NO)

__global__ void cvt_all_kernel(const float* __restrict__ x,
                               const float* __restrict__ wq,
                               const float* __restrict__ wo)
{
    int i = blockIdx.x * blockDim.x + threadIdx.x;
    if (i >= CVT_TOT) return;
    const float4* src;
    __half* dst;
    int j;
    if (i < CVT_NX)                { src = (const float4*)x;  dst = g_xh;  j = i; }
    else if (i < CVT_NX + CVT_NQ)  { src = (const float4*)wq; dst = g_wqh; j = i - CVT_NX; }
    else                           { src = (const float4*)wo; dst = g_woh; j = i - CVT_NX - CVT_NQ; }
    float4 v = src[j];
    *(__half2*)&dst[(size_t)j*4]     = __floats2half2_rn(v.x, v.y);
    *(__half2*)&dst[(size_t)j*4 + 2] = __floats2half2_rn(v.z, v.w);
}

// ---------------------------------------------------------------------------
#define MMA16816(d, a, b0, b1)                                                 \
    asm volatile("mma.sync.aligned.m16n8k16.row.col.f32.f16.f16.f32 "          \
                 "{%0,%1,%2,%3}, {%4,%5,%6,%7}, {%8,%9}, {%0,%1,%2,%3};"       \
                 : "+f"(d[0]), "+f"(d[1]), "+f"(d[2]), "+f"(d[3])              \
                 : "r"(a[0]), "r"(a[1]), "r"(a[2]), "r"(a[3]), "r"(b0), "r"(b1))

#define LDSM4(r0, r1, r2, r3, addr)                                            \
    asm volatile("ldmatrix.sync.aligned.m8n8.x4.shared.b16 {%0,%1,%2,%3}, [%4];" \
                 : "=r"(r0), "=r"(r1), "=r"(r2), "=r"(r3) : "r"(addr))

#define LDSM4T(r0, r1, r2, r3, addr)                                           \
    asm volatile("ldmatrix.sync.aligned.m8n8.x4.trans.shared.b16 {%0,%1,%2,%3}, [%4];" \
                 : "=r"(r0), "=r"(r1), "=r"(r2), "=r"(r3) : "r"(addr))

#define CP16(dst_u32, gptr)                                                    \
    asm volatile("cp.async.cg.shared.global [%0], [%1], 16;"                   \
                 :: "r"(dst_u32), "l"(gptr))
#define CP_COMMIT() asm volatile("cp.async.commit_group;" ::: "memory")
#define CP_WAIT1()  asm volatile("cp.async.wait_group 1;" ::: "memory")

// ---------------------------------------------------------------------------
// fp16 GEMM mainloop, BK=64 (R16): 128x128x64 chunks, 3-stage cp.async,
// ldmatrix.x4 fragment loads, row stride 72 halves (LDSM units 9r mod 32 all
// distinct -> conflict-free). Half the syncs of the BK=32 version.
// ---------------------------------------------------------------------------
#define ARR_HALVES (128*72)
#define STG_HALVES (2*ARR_HALVES)
#define GEMM_SMEM  (3*STG_HALVES*2)   /* 110592 bytes */

#define GEMM_MAINLOOP(Ah, Bh)                                                  \
    extern __shared__ __half dynsmem[];                                        \
    const unsigned sbase = (unsigned)__cvta_generic_to_shared(dynsmem);        \
    const int tid  = threadIdx.x;                                              \
    const int lane = tid & 31;                                                 \
    const int wid  = tid >> 5;                                                 \
    const int warpM = wid & 3;                                                 \
    const int warpN = wid >> 2;                                                \
    const int m0 = blockIdx.y * 128;                                           \
    const int n0 = blockIdx.x * 128;                                           \
    const int g  = lane >> 2;                                                  \
    const int tg = lane & 3;                                                   \
    float acc[2][8][4] = {};                                                   \
    const int rr  = tid >> 3;              /* 0..31 */                         \
    const int cch = (tid & 7) << 3;        /* 0..56 halves */                  \
    const __half* pA = &Ah[(size_t)(m0 + rr) * DMODEL + cch];                  \
    const __half* pB = &Bh[(size_t)(n0 + rr) * DMODEL + cch];                  \
    const unsigned dstoff = (unsigned)(rr * 72 + cch) * 2;                     \
    const unsigned lm_off =                                                    \
        ((unsigned)((lane & 15) * 72 + ((lane >> 4) << 3))) * 2;               \
    const unsigned a_base = sbase + (unsigned)(warpM * 32) * 144 + lm_off;     \
    const unsigned b_base = sbase + (unsigned)(warpN * 64) * 144 + lm_off;     \
    const int nch = DMODEL / 64;                                               \
    ISSUE(0);  CP_COMMIT();                                                    \
    ISSUE(1);  CP_COMMIT();                                                    \
    for (int ch = 0; ch < nch; ch++) {                                         \
        CP_WAIT1();                                                            \
        __syncthreads();                                                       \
        if (ch + 2 < nch) { ISSUE((ch + 2) % 3); }                             \
        CP_COMMIT();                                                           \
        const unsigned st = (unsigned)(ch % 3) * (STG_HALVES * 2);             \
        _Pragma("unroll")                                                      \
        for (int ks = 0; ks < 4; ks++) {                                       \
            const unsigned kb2 = (unsigned)(ks * 16) * 2;                      \
            unsigned ah[2][4];                                                 \
            _Pragma("unroll")                                                  \
            for (int mi = 0; mi < 2; mi++) {                                   \
                unsigned aa = a_base + st + (unsigned)(mi * 16) * 144 + kb2;   \
                LDSM4(ah[mi][0], ah[mi][1], ah[mi][2], ah[mi][3], aa);         \
            }                                                                  \
            _Pragma("unroll")                                                  \
            for (int nip = 0; nip < 4; nip++) {                                \
                unsigned ba = b_base + st + ARR_HALVES*2                       \
                            + (unsigned)(nip * 16) * 144 + kb2;                \
                unsigned b0e, b0o_, b1e, b1o_;                                 \
                LDSM4(b0e, b0o_, b1e, b1o_, ba);                               \
                _Pragma("unroll")                                              \
                for (int mi = 0; mi < 2; mi++) {                               \
                    MMA16816(acc[mi][2*nip],   ah[mi], b0e, b1e);              \
                    MMA16816(acc[mi][2*nip+1], ah[mi], b0o_, b1o_);            \
                }                                                              \
            }                                                                  \
        }                                                                      \
    }

#define ISSUE(s)                                                               \
    do {                                                                       \
        unsigned sb = sbase + (unsigned)(s) * (STG_HALVES * 2);                \
        _Pragma("unroll")                                                      \
        for (int i = 0; i < 4; i++) {                                          \
            unsigned d = sb + dstoff + (unsigned)i * (32*72*2);                \
            CP16(d,                pA + (size_t)i * 32 * DMODEL);              \
            CP16(d + ARR_HALVES*2, pB + (size_t)i * 32 * DMODEL);              \
        }                                                                      \
        pA += 64; pB += 64;                                                    \
    } while (0)

// ---------------------------------------------------------------------------
// QKV GEMM with fused RoPE + dtype-split epilogue.
// ---------------------------------------------------------------------------
__global__ __launch_bounds__(256, 2)
void qkv_gemm_kernel(const int* __restrict__ pos)
{
    GEMM_MAINLOOP(g_xh, g_wqh)

    const int region = (blockIdx.x * 128) >> 10;   // 0=Q, 1=K, 2=V

    #pragma unroll
    for (int mi = 0; mi < 2; mi++) {
        int r0 = m0 + warpM*32 + mi*16 + g;
        float p0 = (float)pos[r0 & (SEQ-1)];
        float p1 = (float)pos[(r0+8) & (SEQ-1)];
        #pragma unroll
        for (int ni = 0; ni < 8; ni++) {
            int cg  = n0 + warpN*64 + ni*8 + tg*2;
            int col = cg & (DMODEL-1);
            float x0 = acc[mi][ni][0], y0 = acc[mi][ni][1];
            float x1 = acc[mi][ni][2], y1 = acc[mi][ni][3];
            if (region < 2) {   // rope for Q and K
                int i = (col & 63) >> 1;
                float inv = expf(-((float)i * (1.0f/32.0f)) * 9.2103403719761836f);
                float sn0, cs0, sn1, cs1;
                sincosf(p0 * inv, &sn0, &cs0);
                sincosf(p1 * inv, &sn1, &cs1);
                float t;
                t = x0*cs0 - y0*sn0; y0 = x0*sn0 + y0*cs0; x0 = t;
                t = x1*cs1 - y1*sn1; y1 = x1*sn1 + y1*cs1; x1 = t;
            }
            size_t o0 = (size_t)r0 * DMODEL + col;
            size_t o1 = (size_t)(r0+8) * DMODEL + col;
            if (region == 0) {
                *(float2*)&g_qf32[o0] = make_float2(x0, y0);
                *(float2*)&g_qf32[o1] = make_float2(x1, y1);
            } else if (region == 1) {
                *(unsigned*)&g_kh[o0] = pack_h(x0, y0);
                *(unsigned*)&g_kh[o1] = pack_h(x1, y1);
            } else {
                *(unsigned*)&g_vh[o0] = pack_h(x0, y0);
                *(unsigned*)&g_vh[o1] = pack_h(x1, y1);
            }
        }
    }
}

// ---------------------------------------------------------------------------
// Output GEMM (generic fp32 epilogue).
// ---------------------------------------------------------------------------
__global__ __launch_bounds__(256, 2)
void out_gemm_kernel(float* __restrict__ out)
{
    GEMM_MAINLOOP(g_ah, g_woh)

    #pragma unroll
    for (int mi = 0; mi < 2; mi++) {
        int r0 = m0 + warpM*32 + mi*16 + g;
        #pragma unroll
        for (int ni = 0; ni < 8; ni++) {
            int c = n0 + warpN*64 + ni*8 + tg*2;
            *(float2*)&out[(size_t)r0 * DMODEL + c] =
                make_float2(acc[mi][ni][0], acc[mi][ni][1]);
            *(float2*)&out[(size_t)(r0+8) * DMODEL + c] =
                make_float2(acc[mi][ni][2], acc[mi][ni][3]);
        }
    }
}
#undef ISSUE

// ---------------------------------------------------------------------------
// Causal flash attention, fp16 tensor cores (unchanged from R14).
// ---------------------------------------------------------------------------
__global__ __launch_bounds__(256)
void attn_mma_kernel()
{
    const int h   = blockIdx.y;
    const int b   = blockIdx.z;
    const int tid = threadIdx.x;
    const int lane = tid & 31;
    const int w   = tid >> 5;
    const int g   = lane >> 2;
    const int tg  = lane & 3;

    __shared__ __half sKh[2][64*72], sVh[2][64*72];

    const unsigned skh0 = (unsigned)__cvta_generic_to_shared(&sKh[0][0]);
    const unsigned skh1 = (unsigned)__cvta_generic_to_shared(&sKh[1][0]);
    const unsigned svh0 = (unsigned)__cvta_generic_to_shared(&sVh[0][0]);
    const unsigned svh1 = (unsigned)__cvta_generic_to_shared(&sVh[1][0]);

    const unsigned koff = ((((lane >> 4) & 1) * 8 + (lane & 7)) * 72
                          + ((lane >> 3) & 1) * 8) * 2;
    const unsigned voff = ((((lane >> 3) & 1) * 8 + (lane & 7)) * 72
                          + ((lane >> 4) & 1) * 8) * 2;

    const float scale = 0.125f * 1.44269504088896f;   // 1/sqrt(64) * log2(e)

    uint4 pk2[2], pv2[2];

    #define GLT(kt_)                                                           \
        _Pragma("unroll")                                                      \
        for (int i = 0; i < 2; i++) {                                          \
            int idx = tid + i*256;                                             \
            int r = idx >> 3, c8 = (idx & 7) << 3;                             \
            size_t base = ((size_t)(b*SEQ) + (kt_)*64 + r)*DMODEL + h*DK + c8; \
            pk2[i] = *(const uint4*)&g_kh[base];                               \
            pv2[i] = *(const uint4*)&g_vh[base];                               \
        }

    #define STS_T(buf_)                                                        \
        _Pragma("unroll")                                                      \
        for (int i = 0; i < 2; i++) {                                          \
            int idx = tid + i*256;                                             \
            int r = idx >> 3, c8 = (idx & 7) << 3;                             \
            *(uint4*)&sKh[buf_][r*72 + c8] = pk2[i];                           \
            *(uint4*)&sVh[buf_][r*72 + c8] = pv2[i];                           \
        }

    #pragma unroll 1
    for (int half = 0; half < 2; half++) {
        const int qt = half ? (NTQ - 1 - blockIdx.x) : blockIdx.x;
        const int qbase = qt * 128;
        const int row0 = qbase + w*16 + g;
        const int row1 = row0 + 8;
        const int wrowmax = qbase + w*16 + 15;

        unsigned qh[4][4];
        {
            const float* q0 = &g_qf32[((size_t)(b*SEQ) + row0)*DMODEL + h*DK];
            const float* q1 = &g_qf32[((size_t)(b*SEQ) + row1)*DMODEL + h*DK];
            #pragma unroll
            for (int kk = 0; kk < 4; kk++) {
                int d0 = kk*16 + 2*tg;
                float2 a0 = *(const float2*)&q0[d0];
                float2 a1 = *(const float2*)&q1[d0];
                float2 a2 = *(const float2*)&q0[d0+8];
                float2 a3 = *(const float2*)&q1[d0+8];
                qh[kk][0] = pack_h(a0.x*scale, a0.y*scale);
                qh[kk][1] = pack_h(a1.x*scale, a1.y*scale);
                qh[kk][2] = pack_h(a2.x*scale, a2.y*scale);
                qh[kk][3] = pack_h(a3.x*scale, a3.y*scale);
            }
        }

        float o[8][4] = {};
        float m0 = -1e30f, m1 = -1e30f, l0 = 0.f, l1 = 0.f;

        const int ntiles = 2*qt + 2;

        GLT(0);
        STS_T(0);
        __syncthreads();

        for (int kt = 0; kt < ntiles; kt++) {
            const int kvbase = kt * 64;
            const int buf = kt & 1;
            const unsigned kb = (buf ? skh1 : skh0) + koff;
            const unsigned vb = (buf ? svh1 : svh0) + voff;

            if (kt + 1 < ntiles) { GLT(kt + 1); }

            if (kvbase <= wrowmax) {
                float sc[8][4] = {};

                #pragma unroll
                for (int kk = 0; kk < 4; kk++) {
                    #pragma unroll
                    for (int ni = 0; ni < 8; ni += 2) {
                        unsigned bb0, bb1, bb2, bb3;
                        unsigned addr = kb + (unsigned)(ni*576 + kk*16) * 2;
                        LDSM4(bb0, bb1, bb2, bb3, addr);
                        MMA16816(sc[ni],   qh[kk], bb0, bb1);
                        MMA16816(sc[ni+1], qh[kk], bb2, bb3);
                    }
                }

                if (kvbase + 63 > row0) {
                    #pragma unroll
                    for (int ni = 0; ni < 8; ni++) {
                        int c = kvbase + ni*8 + 2*tg;
                        if (c     > row0) sc[ni][0] = -1e30f;
                        if (c + 1 > row0) sc[ni][1] = -1e30f;
                        if (c     > row1) sc[ni][2] = -1e30f;
                        if (c + 1 > row1) sc[ni][3] = -1e30f;
                    }
                }

                float t0 = -1e30f, t1 = -1e30f;
                #pragma unroll
                for (int ni = 0; ni < 8; ni++) {
                    t0 = fmaxf(t0, fmaxf(sc[ni][0], sc[ni][1]));
                    t1 = fmaxf(t1, fmaxf(sc[ni][2], sc[ni][3]));
                }
                t0 = fmaxf(t0, __shfl_xor_sync(0xffffffffu, t0, 1));
                t0 = fmaxf(t0, __shfl_xor_sync(0xffffffffu, t0, 2));
                t1 = fmaxf(t1, __shfl_xor_sync(0xffffffffu, t1, 1));
                t1 = fmaxf(t1, __shfl_xor_sync(0xffffffffu, t1, 2));

                float m0n = fmaxf(m0, t0), m1n = fmaxf(m1, t1);
                float c0 = exp2f(m0 - m0n), c1 = exp2f(m1 - m1n);
                m0 = m0n; m1 = m1n;
                l0 *= c0;  l1 *= c1;
                #pragma unroll
                for (int ni = 0; ni < 8; ni++) {
                    o[ni][0] *= c0; o[ni][1] *= c0;
                    o[ni][2] *= c1; o[ni][3] *= c1;
                }

                #pragma unroll
                for (int ni = 0; ni < 8; ni++) {
                    sc[ni][0] = exp2f(sc[ni][0] - m0);
                    sc[ni][1] = exp2f(sc[ni][1] - m0);
                    sc[ni][2] = exp2f(sc[ni][2] - m1);
                    sc[ni][3] = exp2f(sc[ni][3] - m1);
                    l0 += sc[ni][0] + sc[ni][1];
                    l1 += sc[ni][2] + sc[ni][3];
                }

                #pragma unroll
                for (int kk = 0; kk < 4; kk++) {
                    unsigned ph[4];
                    ph[0] = pack_h(sc[2*kk][0],   sc[2*kk][1]);
                    ph[1] = pack_h(sc[2*kk][2],   sc[2*kk][3]);
                    ph[2] = pack_h(sc[2*kk+1][0], sc[2*kk+1][1]);
                    ph[3] = pack_h(sc[2*kk+1][2], sc[2*kk+1][3]);
                    #pragma unroll
                    for (int nd = 0; nd < 8; nd += 2) {
                        unsigned bb0, bb1, bb2, bb3;
                        unsigned addr = vb + (unsigned)(kk*16*72 + nd*8) * 2;
                        LDSM4T(bb0, bb1, bb2, bb3, addr);
                        MMA16816(o[nd],   ph, bb0, bb1);
                        MMA16816(o[nd+1], ph, bb2, bb3);
                    }
                }
            }

            if (kt + 1 < ntiles) { STS_T(buf ^ 1); }
            __syncthreads();
        }

        l0 += __shfl_xor_sync(0xffffffffu, l0, 1);
        l0 += __shfl_xor_sync(0xffffffffu, l0, 2);
        l1 += __shfl_xor_sync(0xffffffffu, l1, 1);
        l1 += __shfl_xor_sync(0xffffffffu, l1, 2);
        float inv0 = 1.f / l0, inv1 = 1.f / l1;

        size_t base0 = ((size_t)(b*SEQ) + row0)*DMODEL + h*DK;
        size_t base1 = ((size_t)(b*SEQ) + row1)*DMODEL + h*DK;
        #pragma unroll
        for (int nd = 0; nd < 8; nd++) {
            int c = nd*8 + 2*tg;
            *(unsigned*)&g_ah[base0 + c] = pack_h(o[nd][0]*inv0, o[nd][1]*inv0);
            *(unsigned*)&g_ah[base1 + c] = pack_h(o[nd][2]*inv1, o[nd][3]*inv1);
        }
    }
    #undef GLT
    #undef STS_T
}

// ---------------------------------------------------------------------------
extern "C" void kernel_launch(void* const* d_in, const int* in_sizes, int n_in,
                              void* d_out, int out_size)
{
    const float* x      = (const float*)d_in[0];
    const int*   pos    = (const int*)d_in[1];
    const float* w_qkv  = (const float*)d_in[2];
    const float* w_o    = (const float*)d_in[3];
    float*       out    = (float*)d_out;

    cudaFuncSetAttribute(qkv_gemm_kernel,
                         cudaFuncAttributeMaxDynamicSharedMemorySize, GEMM_SMEM);
    cudaFuncSetAttribute(out_gemm_kernel,
                         cudaFuncAttributeMaxDynamicSharedMemorySize, GEMM_SMEM);

    // 0) fp16 converts (single fused launch)
    cvt_all_kernel<<<(CVT_TOT + 255)/256, 256>>>(x, w_qkv, w_o);

    // 1) QKV projection + fused RoPE + dtype split (BK=64)
    {
        dim3 grid(E3 / 128, NTOK / 128);
        qkv_gemm_kernel<<<grid, 256, GEMM_SMEM>>>(pos);
    }
    // 2) Causal flash attention
    {
        dim3 grid(NTQ / 2, NHEADS, BATCH);
        attn_mma_kernel<<<grid, 256>>>();
    }
    // 3) Output projection (BK=64)
    {
        dim3 grid(DMODEL / 128, NTOK / 128);
        out_gemm_kernel<<<grid, 256, GEMM_SMEM>>>(out);
    }
}